// round 2
// baseline (speedup 1.0000x reference)
#include <cuda_runtime.h>
#include <math.h>
#include <float.h>

#define BB 64
#define QQ 900
#define TT 128
#define C1 14   // NUM_CLASSES+1

// Scratch (static device globals; no allocation)
__device__ float g_cost[(size_t)BB*TT*QQ];   // cost[b][t][q]
__device__ float g_lse[BB*QQ];
__device__ int   g_pred[BB*TT];              // matched query index per (b,t)
__device__ float g_partial[BB];

// ---------------------------------------------------------------------------
// Kernel 1: cost matrix + logsumexp
// grid: (ceil(Q/256), B), block: 256
// ---------------------------------------------------------------------------
__global__ void __launch_bounds__(256) cost_kernel(
    const float* __restrict__ pc, const float* __restrict__ pb,
    const int* __restrict__ tl, const float* __restrict__ tb)
{
    int b = blockIdx.y;
    int tid = threadIdx.x;
    int q = blockIdx.x * 256 + tid;

    __shared__ int   slab[TT];
    __shared__ float stb[TT * 4];
    __shared__ float sprob[256 * 15];   // stride 15 -> conflict-free dynamic index

    for (int t = tid; t < TT; t += 256) {
        slab[t] = tl[b * TT + t];
        const float* tb4 = tb + ((size_t)b * TT + t) * 4;
        stb[t * 4 + 0] = tb4[0];
        stb[t * 4 + 1] = tb4[1];
        stb[t * 4 + 2] = tb4[2];
        stb[t * 4 + 3] = tb4[3];
    }

    float px = 0.f, py = 0.f, pw = 0.f, ph = 0.f;
    if (q < QQ) {
        const float* lg = pc + ((size_t)b * QQ + q) * C1;
        float l[C1];
        float m = -FLT_MAX;
        #pragma unroll
        for (int c = 0; c < C1; c++) { l[c] = lg[c]; m = fmaxf(m, l[c]); }
        float s = 0.f;
        #pragma unroll
        for (int c = 0; c < C1; c++) {
            float e = expf(l[c] - m);
            sprob[tid * 15 + c] = e;
            s += e;
        }
        float inv = -1.0f / s;   // store NEGATIVE prob (class cost is -prob)
        #pragma unroll
        for (int c = 0; c < C1; c++) sprob[tid * 15 + c] *= inv;
        g_lse[b * QQ + q] = m + logf(s);

        const float* pb4 = pb + ((size_t)b * QQ + q) * 4;
        px = pb4[0]; py = pb4[1]; pw = pb4[2]; ph = pb4[3];
    }
    __syncthreads();
    if (q >= QQ) return;

    float* out = g_cost + (size_t)b * TT * QQ + q;
    #pragma unroll 4
    for (int t = 0; t < TT; t++) {
        float tx = stb[t * 4 + 0], ty = stb[t * 4 + 1];
        float tw = stb[t * 4 + 2], th = stb[t * 4 + 3];
        float l1 = fabsf(px - tx) + fabsf(py - ty) + fabsf(pw - tw) + fabsf(ph - th);
        float cc = sprob[tid * 15 + slab[t]];
        out[(size_t)t * QQ] = cc + l1;
    }
}

// ---------------------------------------------------------------------------
// Kernel 2: exact Hungarian (Jonker-Volgenant), one block per batch.
// n=T=128 rows (targets), m=Q=900 cols (queries). Doubles for duals to
// reproduce the reference float64 arithmetic.
// ---------------------------------------------------------------------------
__global__ void __launch_bounds__(256) hungarian_kernel()
{
    int b = blockIdx.x;
    const float* cost = g_cost + (size_t)b * TT * QQ;

    __shared__ double v[QQ + 1];
    __shared__ double minv[QQ + 1];
    __shared__ double u[TT + 1];
    __shared__ short  p[QQ + 1];
    __shared__ short  way[QQ + 1];
    __shared__ unsigned char used[QQ + 1];
    __shared__ double s_delta;
    __shared__ int    s_j0;
    __shared__ double red_v[8];
    __shared__ int    red_j[8];

    int tid = threadIdx.x;
    int lane = tid & 31, wid = tid >> 5;

    for (int j = tid; j <= QQ; j += 256) { v[j] = 0.0; p[j] = 0; }
    for (int i = tid; i <= TT; i += 256) u[i] = 0.0;
    __syncthreads();

    for (int i = 1; i <= TT; i++) {
        for (int j = tid; j <= QQ; j += 256) { minv[j] = DBL_MAX; used[j] = 0; }
        if (tid == 0) { p[0] = (short)i; s_j0 = 0; }
        __syncthreads();

        while (1) {
            int j0 = s_j0;
            int i0 = p[j0];
            double ui0 = u[i0];
            const float* crow = cost + (size_t)(i0 - 1) * QQ;
            if (tid == 0) used[j0] = 1;
            __syncthreads();

            // scan free columns: update minv/way, track block argmin
            double bv = DBL_MAX;
            int    bj = 0x7fffffff;
            for (int j = tid + 1; j <= QQ; j += 256) {
                if (!used[j]) {
                    double cur = (double)crow[j - 1] - ui0 - v[j];
                    double mv = minv[j];
                    if (cur < mv) { mv = cur; minv[j] = cur; way[j] = (short)j0; }
                    if (mv < bv) { bv = mv; bj = j; }
                }
            }
            // warp reduce (min, tie -> lowest column index, matching np.argmin)
            #pragma unroll
            for (int o = 16; o; o >>= 1) {
                double ov = __shfl_down_sync(0xffffffffu, bv, o);
                int    oj = __shfl_down_sync(0xffffffffu, bj, o);
                if (ov < bv || (ov == bv && oj < bj)) { bv = ov; bj = oj; }
            }
            if (lane == 0) { red_v[wid] = bv; red_j[wid] = bj; }
            __syncthreads();
            if (wid == 0) {
                bv = (lane < 8) ? red_v[lane] : DBL_MAX;
                bj = (lane < 8) ? red_j[lane] : 0x7fffffff;
                #pragma unroll
                for (int o = 4; o; o >>= 1) {
                    double ov = __shfl_down_sync(0xffffffffu, bv, o);
                    int    oj = __shfl_down_sync(0xffffffffu, bj, o);
                    if (ov < bv || (ov == bv && oj < bj)) { bv = ov; bj = oj; }
                }
                if (lane == 0) { s_delta = bv; s_j0 = bj; }
            }
            __syncthreads();

            double delta = s_delta;
            int j1 = s_j0;
            // dual update: u[p[used]] += delta, v[used] -= delta, minv[free] -= delta
            for (int j = tid; j <= QQ; j += 256) {
                if (used[j]) { u[p[j]] += delta; v[j] -= delta; }
                else         { minv[j] -= delta; }
            }
            __syncthreads();
            if (p[j1] == 0) break;
        }

        // augment along alternating path (serial, trivial length)
        if (tid == 0) {
            int j0 = s_j0;
            while (j0) {
                int jn = way[j0];
                p[j0] = p[jn];
                j0 = jn;
            }
        }
        __syncthreads();
    }

    // emit pred_idx: column j (query j-1) assigned to row p[j] (target p[j]-1)
    for (int j = tid + 1; j <= QQ; j += 256) {
        int r = p[j];
        if (r > 0) g_pred[b * TT + (r - 1)] = j - 1;
    }
}

// ---------------------------------------------------------------------------
// Kernel 3: per-batch losses (bbox L1 + GIoU + weighted CE), one block/batch
// ---------------------------------------------------------------------------
__global__ void __launch_bounds__(256) loss_kernel(
    const float* __restrict__ pc, const float* __restrict__ pb,
    const int* __restrict__ tl, const float* __restrict__ tb)
{
    int b = blockIdx.x, tid = threadIdx.x;
    int lane = tid & 31, wid = tid >> 5;

    __shared__ short tc[QQ];
    __shared__ double red[8][4];

    for (int q = tid; q < QQ; q += 256) tc[q] = 13;
    __syncthreads();

    double l1sum = 0.0, gsum = 0.0;
    if (tid < TT) {
        int t = tid;
        int q = g_pred[b * TT + t];
        int lab = tl[b * TT + t];
        tc[q] = (short)lab;

        const float* pbx = pb + ((size_t)b * QQ + q) * 4;
        const float* tbx = tb + ((size_t)b * TT + t) * 4;
        float px = pbx[0], py = pbx[1], pw = pbx[2], ph = pbx[3];
        float tx = tbx[0], ty = tbx[1], tw = tbx[2], th = tbx[3];

        l1sum = (double)(fabsf(px - tx) + fabsf(py - ty) +
                         fabsf(pw - tw) + fabsf(ph - th));

        float p1x = px - 0.5f * pw, p1y = py - 0.5f * ph;
        float p2x = px + 0.5f * pw, p2y = py + 0.5f * ph;
        float t1x = tx - 0.5f * tw, t1y = ty - 0.5f * th;
        float t2x = tx + 0.5f * tw, t2y = ty + 0.5f * th;
        float a1 = (p2x - p1x) * (p2y - p1y);
        float a2 = (t2x - t1x) * (t2y - t1y);
        float ltx = fmaxf(p1x, t1x), lty = fmaxf(p1y, t1y);
        float rbx = fminf(p2x, t2x), rby = fminf(p2y, t2y);
        float iw = fmaxf(rbx - ltx, 0.f), ih = fmaxf(rby - lty, 0.f);
        float inter = iw * ih;
        float uni = a1 + a2 - inter;
        float iou = inter / uni;
        float cx1 = fminf(p1x, t1x), cy1 = fminf(p1y, t1y);
        float cx2 = fmaxf(p2x, t2x), cy2 = fmaxf(p2y, t2y);
        float ac = (cx2 - cx1) * (cy2 - cy1);
        gsum = (double)(iou - (ac - uni) / ac);
    }
    __syncthreads();

    double clsum = 0.0, wsum = 0.0;
    for (int q = tid; q < QQ; q += 256) {
        int c = tc[q];
        float w = (c == 13) ? 0.05f : 1.0f;
        float nll = g_lse[b * QQ + q] - pc[((size_t)b * QQ + q) * C1 + c];
        clsum += (double)(w * nll);
        wsum  += (double)w;
    }

    // block reduce 4 doubles
    #pragma unroll
    for (int o = 16; o; o >>= 1) {
        l1sum += __shfl_down_sync(0xffffffffu, l1sum, o);
        gsum  += __shfl_down_sync(0xffffffffu, gsum, o);
        clsum += __shfl_down_sync(0xffffffffu, clsum, o);
        wsum  += __shfl_down_sync(0xffffffffu, wsum, o);
    }
    if (lane == 0) { red[wid][0] = l1sum; red[wid][1] = gsum; red[wid][2] = clsum; red[wid][3] = wsum; }
    __syncthreads();
    if (tid == 0) {
        double a = 0, g = 0, c = 0, w = 0;
        #pragma unroll
        for (int k = 0; k < 8; k++) { a += red[k][0]; g += red[k][1]; c += red[k][2]; w += red[k][3]; }
        double l1mean = a / (double)(TT * 4);
        double bbox = 5.0 * l1mean + 2.0 * (1.0 - g / (double)TT);
        double cls = c / w;
        g_partial[b] = (float)(bbox + cls);
    }
}

// ---------------------------------------------------------------------------
// Kernel 4: deterministic final sum
// ---------------------------------------------------------------------------
__global__ void finalize_kernel(float* __restrict__ out)
{
    int tid = threadIdx.x;
    __shared__ double sw[2];
    double s = (tid < BB) ? (double)g_partial[tid] : 0.0;
    #pragma unroll
    for (int o = 16; o; o >>= 1) s += __shfl_down_sync(0xffffffffu, s, o);
    if ((tid & 31) == 0) sw[tid >> 5] = s;
    __syncthreads();
    if (tid == 0) out[0] = (float)((sw[0] + sw[1]) / (double)(BB * TT));
}

// ---------------------------------------------------------------------------
extern "C" void kernel_launch(void* const* d_in, const int* in_sizes, int n_in,
                              void* d_out, int out_size)
{
    const float* pc = (const float*)d_in[0];  // predicted_class [B,Q,14]
    const float* pb = (const float*)d_in[1];  // predicted_bbox  [B,Q,4]
    const int*   tl = (const int*)d_in[2];    // target_labels   [B,T]
    const float* tb = (const float*)d_in[3];  // target_boxes    [B,T,4]

    cost_kernel<<<dim3((QQ + 255) / 256, BB), 256>>>(pc, pb, tl, tb);
    hungarian_kernel<<<BB, 256>>>();
    loss_kernel<<<BB, 256>>>(pc, pb, tl, tb);
    finalize_kernel<<<1, 64>>>((float*)d_out);
}